// round 10
// baseline (speedup 1.0000x reference)
#include <cuda_runtime.h>
#include <stdint.h>

#define N_NODES 50000
#define N_EDGES 800000
#define D 96
#define DC 24              // D / 4 (float4 chunks per row)
#define XS_STRIDE 25       // padded row stride in float4 (bank decorrelation)
#define GEMM_ROWS 64       // rows per block
#define GEMM_THREADS 192   // 12 col-groups x 16 row-groups
#define GEMM_SMEM ((D * DC + GEMM_ROWS * XS_STRIDE) * 16)  // Ws + Xs bytes = 62464

// Scratch (device globals; no allocation allowed)
__device__ int   g_is64;
__device__ float g_deg[N_NODES];
__device__ float g_dinv[N_NODES];
__device__ float g_h[(size_t)N_NODES * D];     // stores h * dinv[row]

__device__ __forceinline__ int load_idx(const void* ei, size_t k) {
    return g_is64 ? (int)((const long long*)ei)[k] : ((const int*)ei)[k];
}

// packed f32x2 helpers (sm_103a FFMA2 — PTX only)
__device__ __forceinline__ unsigned long long pack2(float x, float y) {
    unsigned long long p;
    asm("mov.b64 %0, {%1, %2};" : "=l"(p) : "f"(x), "f"(y));
    return p;
}
__device__ __forceinline__ void fma2(unsigned long long& acc,
                                     unsigned long long a,
                                     unsigned long long b) {
    asm("fma.rn.f32x2 %0, %1, %2, %0;" : "+l"(acc) : "l"(a), "l"(b));
}
__device__ __forceinline__ void unpack2(unsigned long long p, float& x, float& y) {
    asm("mov.b64 {%0, %1}, %2;" : "=f"(x), "=f"(y) : "l"(p));
}

// ---------------------------------------------------------------------------
// 1. init: deg = 1 (self loop weight); thread 0 detects edge_index dtype.
//    int64 values < 2^31 have all-zero odd int32 words; random int32 ids don't.
// ---------------------------------------------------------------------------
__global__ void init_kernel(const int* __restrict__ ei32) {
    int i = blockIdx.x * blockDim.x + threadIdx.x;
    if (i < N_NODES) g_deg[i] = 1.0f;
    if (i == 0) {
        int looks64 = 1, any_nonzero = 0;
        #pragma unroll
        for (int k = 0; k < 64; k++) {
            if (ei32[2 * k + 1] != 0) looks64 = 0;
            if (ei32[2 * k] != 0) any_nonzero = 1;
        }
        g_is64 = (looks64 && any_nonzero) ? 1 : 0;
    }
}

// ---------------------------------------------------------------------------
// 2. deg[col] += ew
// ---------------------------------------------------------------------------
__global__ void accum_deg_kernel(const void* __restrict__ ei,
                                 const float* __restrict__ ew) {
    int e = blockIdx.x * blockDim.x + threadIdx.x;
    if (e < N_EDGES) {
        int col = load_idx(ei, (size_t)N_EDGES + e);
        atomicAdd(&g_deg[col], ew[e]);
    }
}

// ---------------------------------------------------------------------------
// 3. dinv = rsqrt(deg)   (deg >= 1 always)
// ---------------------------------------------------------------------------
__global__ void dinv_kernel() {
    int i = blockIdx.x * blockDim.x + threadIdx.x;
    if (i < N_NODES) g_dinv[i] = rsqrtf(g_deg[i]);
}

// ---------------------------------------------------------------------------
// 4. GEMM + epilogue:  h' = (x @ W) * dinv[row]  -> g_h
//                      out[row] = b + h' * dinv[row]   (self loop + bias)
//    4x8 thread tiles (4 rows x 2 float4 chunks), FFMA2 inner loop,
//    62.5KB dynamic smem -> 3 blocks/SM.
// ---------------------------------------------------------------------------
__global__ __launch_bounds__(GEMM_THREADS)
void gemm_kernel(const float* __restrict__ x, const float* __restrict__ W,
                 const float* __restrict__ b, float* __restrict__ out) {
    extern __shared__ float smem[];
    float4* Ws4 = (float4*)smem;                       // [D][DC]
    float4* Xs4 = (float4*)(smem + D * D);             // [GEMM_ROWS][XS_STRIDE]

    int tid = threadIdx.x;
    int row0 = blockIdx.x * GEMM_ROWS;

    const float4* W4 = (const float4*)W;
    #pragma unroll
    for (int i = tid; i < D * DC; i += GEMM_THREADS) Ws4[i] = W4[i];

    const float4* X4 = (const float4*)x;
    #pragma unroll
    for (int i = tid; i < GEMM_ROWS * DC; i += GEMM_THREADS) {
        int r = i / DC;
        int c = i - r * DC;
        int gr = row0 + r;
        Xs4[r * XS_STRIDE + c] = (gr < N_NODES) ? X4[(size_t)gr * DC + c]
                                                : make_float4(0.f, 0.f, 0.f, 0.f);
    }
    __syncthreads();

    int tx = tid % 12;       // col group: float4 chunks 2*tx, 2*tx+1
    int ty = tid / 12;       // row group 0..15
    int rbase = ty * 4;
    int c0 = 2 * tx, c1 = 2 * tx + 1;

    // acc[r][0..3] = {XY chunk0, ZW chunk0, XY chunk1, ZW chunk1}
    unsigned long long acc[4][4];
    #pragma unroll
    for (int r = 0; r < 4; r++)
        #pragma unroll
        for (int q = 0; q < 4; q++) acc[r][q] = 0ull;

    #pragma unroll 2
    for (int kc = 0; kc < DC; kc++) {
        float4 xv[4];
        #pragma unroll
        for (int r = 0; r < 4; r++) xv[r] = Xs4[(rbase + r) * XS_STRIDE + kc];
        #pragma unroll
        for (int kk = 0; kk < 4; kk++) {
            float4 wv0 = Ws4[(kc * 4 + kk) * DC + c0];
            float4 wv1 = Ws4[(kc * 4 + kk) * DC + c1];
            unsigned long long w0XY = pack2(wv0.x, wv0.y);
            unsigned long long w0ZW = pack2(wv0.z, wv0.w);
            unsigned long long w1XY = pack2(wv1.x, wv1.y);
            unsigned long long w1ZW = pack2(wv1.z, wv1.w);
            #pragma unroll
            for (int r = 0; r < 4; r++) {
                float a = ((const float*)&xv[r])[kk];
                unsigned long long aa = pack2(a, a);
                fma2(acc[r][0], aa, w0XY);
                fma2(acc[r][1], aa, w0ZW);
                fma2(acc[r][2], aa, w1XY);
                fma2(acc[r][3], aa, w1ZW);
            }
        }
    }

    float4 bv0 = ((const float4*)b)[c0];
    float4 bv1 = ((const float4*)b)[c1];
    float4* H4 = (float4*)g_h;
    float4* O4 = (float4*)out;
    #pragma unroll
    for (int r = 0; r < 4; r++) {
        int gr = row0 + rbase + r;
        if (gr < N_NODES) {
            float s = g_dinv[gr];
            float4 h0, h1;
            unpack2(acc[r][0], h0.x, h0.y);
            unpack2(acc[r][1], h0.z, h0.w);
            unpack2(acc[r][2], h1.x, h1.y);
            unpack2(acc[r][3], h1.z, h1.w);
            h0.x *= s; h0.y *= s; h0.z *= s; h0.w *= s;
            h1.x *= s; h1.y *= s; h1.z *= s; h1.w *= s;
            H4[(size_t)gr * DC + c0] = h0;
            H4[(size_t)gr * DC + c1] = h1;
            float4 o0, o1;   // b + h*dinv^2
            o0.x = bv0.x + h0.x * s; o0.y = bv0.y + h0.y * s;
            o0.z = bv0.z + h0.z * s; o0.w = bv0.w + h0.w * s;
            o1.x = bv1.x + h1.x * s; o1.y = bv1.y + h1.y * s;
            o1.z = bv1.z + h1.z * s; o1.w = bv1.w + h1.w * s;
            O4[(size_t)gr * DC + c0] = o0;
            O4[(size_t)gr * DC + c1] = o1;
        }
    }
}

// ---------------------------------------------------------------------------
// 5. Scatter: 12 threads per edge, 2 float4 chunks each (c and c+12).
//    out[col] += h'[row] * (ew[e] * dinv[col])   via red.global.add.v4.f32
// ---------------------------------------------------------------------------
__global__ __launch_bounds__(256)
void scatter_kernel(const void* __restrict__ ei,
                    const float* __restrict__ ew,
                    float* __restrict__ out) {
    int idx = blockIdx.x * blockDim.x + threadIdx.x;
    if (idx >= N_EDGES * 12) return;
    int e = idx / 12;
    int c = idx - e * 12;            // chunk pair: c and c+12
    int row = load_idx(ei, e);
    int col = load_idx(ei, (size_t)N_EDGES + e);
    float nrm = ew[e] * g_dinv[col];

    const float4* H4 = (const float4*)g_h;
    float4 hv0 = H4[(size_t)row * DC + c];
    float4 hv1 = H4[(size_t)row * DC + c + 12];
    float* base = out + (size_t)col * D;

    float a0 = hv0.x * nrm, a1 = hv0.y * nrm, a2 = hv0.z * nrm, a3 = hv0.w * nrm;
    asm volatile("red.global.add.v4.f32 [%0], {%1, %2, %3, %4};"
                 :: "l"(base + c * 4), "f"(a0), "f"(a1), "f"(a2), "f"(a3)
                 : "memory");
    float b0 = hv1.x * nrm, b1 = hv1.y * nrm, b2 = hv1.z * nrm, b3 = hv1.w * nrm;
    asm volatile("red.global.add.v4.f32 [%0], {%1, %2, %3, %4};"
                 :: "l"(base + (c + 12) * 4), "f"(b0), "f"(b1), "f"(b2), "f"(b3)
                 : "memory");
}

// ---------------------------------------------------------------------------
// Launch.  Inputs: x[N*96] f32, edge_index[2*E] int32/int64, edge_weight[E] f32,
//                  W[96*96] f32, b[96] f32.  Output: [N*96] f32.
// ---------------------------------------------------------------------------
extern "C" void kernel_launch(void* const* d_in, const int* in_sizes, int n_in,
                              void* d_out, int out_size) {
    const float* x = (const float*)d_in[0];
    const void* ei = d_in[1];
    const float* ew = (const float*)d_in[2];
    const float* W = (const float*)d_in[3];
    const float* b = (const float*)d_in[4];
    float* out = (float*)d_out;

    static int smem_set = 0;
    if (!smem_set) {
        cudaFuncSetAttribute(gemm_kernel,
                             cudaFuncAttributeMaxDynamicSharedMemorySize,
                             GEMM_SMEM);
        smem_set = 1;
    }

    init_kernel<<<(N_NODES + 255) / 256, 256>>>((const int*)ei);
    accum_deg_kernel<<<(N_EDGES + 255) / 256, 256>>>(ei, ew);
    dinv_kernel<<<(N_NODES + 255) / 256, 256>>>();
    gemm_kernel<<<(N_NODES + GEMM_ROWS - 1) / GEMM_ROWS, GEMM_THREADS, GEMM_SMEM>>>(x, W, b, out);
    scatter_kernel<<<(N_EDGES * 12 + 255) / 256, 256>>>(ei, ew, out);
}

// round 12
// speedup vs baseline: 1.7167x; 1.7167x over previous
#include <cuda_runtime.h>
#include <stdint.h>

#define N_NODES 50000
#define N_EDGES 800000
#define D 96
#define DC 24              // D / 4 (float4 chunks per row)
#define XS_STRIDE 25       // padded row stride in float4
#define GEMM_ROWS 128      // rows per block
#define GEMM_THREADS 192   // 12 col-groups x 16 row-groups
#define GEMM_SMEM ((D * DC + GEMM_ROWS * XS_STRIDE) * 16)  // Ws + Xs bytes

// Scratch (device globals; no allocation allowed)
__device__ int   g_is64;
__device__ float g_deg[N_NODES];
__device__ float g_dinv[N_NODES];
__device__ float g_h[(size_t)N_NODES * D];     // stores h * dinv[row]

__device__ __forceinline__ int load_idx(const void* ei, size_t k) {
    return g_is64 ? (int)((const long long*)ei)[k] : ((const int*)ei)[k];
}

// packed f32x2 helpers (sm_103a FFMA2 — PTX only)
__device__ __forceinline__ unsigned long long pack2(float x, float y) {
    unsigned long long p;
    asm("mov.b64 %0, {%1, %2};" : "=l"(p) : "f"(x), "f"(y));
    return p;
}
__device__ __forceinline__ void fma2(unsigned long long& acc,
                                     unsigned long long a,
                                     unsigned long long b) {
    asm("fma.rn.f32x2 %0, %1, %2, %0;" : "+l"(acc) : "l"(a), "l"(b));
}
__device__ __forceinline__ void unpack2(unsigned long long p, float& x, float& y) {
    asm("mov.b64 {%0, %1}, %2;" : "=f"(x), "=f"(y) : "l"(p));
}

// ---------------------------------------------------------------------------
// 1. init: deg = 1 (self loop weight); thread 0 detects edge_index dtype.
//    int64 values < 2^31 have all-zero odd int32 words; random int32 ids don't.
// ---------------------------------------------------------------------------
__global__ void init_kernel(const int* __restrict__ ei32) {
    int i = blockIdx.x * blockDim.x + threadIdx.x;
    if (i < N_NODES) g_deg[i] = 1.0f;
    if (i == 0) {
        int looks64 = 1, any_nonzero = 0;
        #pragma unroll
        for (int k = 0; k < 64; k++) {
            if (ei32[2 * k + 1] != 0) looks64 = 0;
            if (ei32[2 * k] != 0) any_nonzero = 1;
        }
        g_is64 = (looks64 && any_nonzero) ? 1 : 0;
    }
}

// ---------------------------------------------------------------------------
// 2. deg[col] += ew
// ---------------------------------------------------------------------------
__global__ void accum_deg_kernel(const void* __restrict__ ei,
                                 const float* __restrict__ ew) {
    int e = blockIdx.x * blockDim.x + threadIdx.x;
    if (e < N_EDGES) {
        int col = load_idx(ei, (size_t)N_EDGES + e);
        atomicAdd(&g_deg[col], ew[e]);
    }
}

// ---------------------------------------------------------------------------
// 3. dinv = rsqrt(deg)   (deg >= 1 always)
// ---------------------------------------------------------------------------
__global__ void dinv_kernel() {
    int i = blockIdx.x * blockDim.x + threadIdx.x;
    if (i < N_NODES) g_dinv[i] = rsqrtf(g_deg[i]);
}

// ---------------------------------------------------------------------------
// 4. GEMM + epilogue:  h' = (x @ W) * dinv[row]  -> g_h
//                      out[row] = b + h' * dinv[row]   (self loop + bias)
//    8x8 thread tiles, FFMA2 inner loop, 88KB dynamic smem.  (R8 config)
// ---------------------------------------------------------------------------
__global__ __launch_bounds__(GEMM_THREADS)
void gemm_kernel(const float* __restrict__ x, const float* __restrict__ W,
                 const float* __restrict__ b, float* __restrict__ out) {
    extern __shared__ float smem[];
    float4* Ws4 = (float4*)smem;                       // [D][DC]
    float4* Xs4 = (float4*)(smem + D * D);             // [GEMM_ROWS][XS_STRIDE]

    int tid = threadIdx.x;
    int row0 = blockIdx.x * GEMM_ROWS;

    const float4* W4 = (const float4*)W;
    #pragma unroll
    for (int i = tid; i < D * DC; i += GEMM_THREADS) Ws4[i] = W4[i];

    const float4* X4 = (const float4*)x;
    #pragma unroll
    for (int i = tid; i < GEMM_ROWS * DC; i += GEMM_THREADS) {
        int r = i / DC;
        int c = i - r * DC;
        int gr = row0 + r;
        Xs4[r * XS_STRIDE + c] = (gr < N_NODES) ? X4[(size_t)gr * DC + c]
                                                : make_float4(0.f, 0.f, 0.f, 0.f);
    }
    __syncthreads();

    int tx = tid % 12;       // col group: float4 chunks 2*tx, 2*tx+1
    int ty = tid / 12;       // row group 0..15
    int rbase = ty * 8;
    int c0 = 2 * tx, c1 = 2 * tx + 1;

    unsigned long long acc[8][4];
    #pragma unroll
    for (int r = 0; r < 8; r++)
        #pragma unroll
        for (int q = 0; q < 4; q++) acc[r][q] = 0ull;

    #pragma unroll 2
    for (int kc = 0; kc < DC; kc++) {
        float4 xv[8];
        #pragma unroll
        for (int r = 0; r < 8; r++) xv[r] = Xs4[(rbase + r) * XS_STRIDE + kc];
        #pragma unroll
        for (int kk = 0; kk < 4; kk++) {
            float4 wv0 = Ws4[(kc * 4 + kk) * DC + c0];
            float4 wv1 = Ws4[(kc * 4 + kk) * DC + c1];
            unsigned long long w0XY = pack2(wv0.x, wv0.y);
            unsigned long long w0ZW = pack2(wv0.z, wv0.w);
            unsigned long long w1XY = pack2(wv1.x, wv1.y);
            unsigned long long w1ZW = pack2(wv1.z, wv1.w);
            #pragma unroll
            for (int r = 0; r < 8; r++) {
                float a = ((const float*)&xv[r])[kk];
                unsigned long long aa = pack2(a, a);
                fma2(acc[r][0], aa, w0XY);
                fma2(acc[r][1], aa, w0ZW);
                fma2(acc[r][2], aa, w1XY);
                fma2(acc[r][3], aa, w1ZW);
            }
        }
    }

    float4 bv0 = ((const float4*)b)[c0];
    float4 bv1 = ((const float4*)b)[c1];
    float4* H4 = (float4*)g_h;
    float4* O4 = (float4*)out;
    #pragma unroll
    for (int r = 0; r < 8; r++) {
        int gr = row0 + rbase + r;
        if (gr < N_NODES) {
            float s = g_dinv[gr];
            float4 h0, h1;
            unpack2(acc[r][0], h0.x, h0.y);
            unpack2(acc[r][1], h0.z, h0.w);
            unpack2(acc[r][2], h1.x, h1.y);
            unpack2(acc[r][3], h1.z, h1.w);
            h0.x *= s; h0.y *= s; h0.z *= s; h0.w *= s;
            h1.x *= s; h1.y *= s; h1.z *= s; h1.w *= s;
            H4[(size_t)gr * DC + c0] = h0;
            H4[(size_t)gr * DC + c1] = h1;
            float4 o0, o1;   // b + h*dinv^2
            o0.x = bv0.x + h0.x * s; o0.y = bv0.y + h0.y * s;
            o0.z = bv0.z + h0.z * s; o0.w = bv0.w + h0.w * s;
            o1.x = bv1.x + h1.x * s; o1.y = bv1.y + h1.y * s;
            o1.z = bv1.z + h1.z * s; o1.w = bv1.w + h1.w * s;
            O4[(size_t)gr * DC + c0] = o0;
            O4[(size_t)gr * DC + c1] = o1;
        }
    }
}

// ---------------------------------------------------------------------------
// 5. Scatter: thread t -> edge t/24, chunk t%24 (R8 mapping),
//    but with dinv table load (no per-thread rsqrt / MUFU pressure).
//    out[col] += h'[row] * (ew[e] * dinv[col])   via red.global.add.v4.f32
// ---------------------------------------------------------------------------
__global__ __launch_bounds__(256)
void scatter_kernel(const void* __restrict__ ei,
                    const float* __restrict__ ew,
                    float* __restrict__ out) {
    int idx = blockIdx.x * blockDim.x + threadIdx.x;
    if (idx >= N_EDGES * DC) return;
    int e = idx / DC;
    int c = idx - e * DC;
    int row = load_idx(ei, e);
    int col = load_idx(ei, (size_t)N_EDGES + e);
    float nrm = ew[e] * g_dinv[col];
    float4 hv = ((const float4*)g_h)[(size_t)row * DC + c];
    float mx = hv.x * nrm, my = hv.y * nrm, mz = hv.z * nrm, mw = hv.w * nrm;
    float* addr = out + (size_t)col * D + c * 4;
    asm volatile("red.global.add.v4.f32 [%0], {%1, %2, %3, %4};"
                 :: "l"(addr), "f"(mx), "f"(my), "f"(mz), "f"(mw)
                 : "memory");
}

// ---------------------------------------------------------------------------
// Launch.  Inputs: x[N*96] f32, edge_index[2*E] int32/int64, edge_weight[E] f32,
//                  W[96*96] f32, b[96] f32.  Output: [N*96] f32.
// ---------------------------------------------------------------------------
extern "C" void kernel_launch(void* const* d_in, const int* in_sizes, int n_in,
                              void* d_out, int out_size) {
    const float* x = (const float*)d_in[0];
    const void* ei = d_in[1];
    const float* ew = (const float*)d_in[2];
    const float* W = (const float*)d_in[3];
    const float* b = (const float*)d_in[4];
    float* out = (float*)d_out;

    static int smem_set = 0;
    if (!smem_set) {
        cudaFuncSetAttribute(gemm_kernel,
                             cudaFuncAttributeMaxDynamicSharedMemorySize,
                             GEMM_SMEM);
        smem_set = 1;
    }

    init_kernel<<<(N_NODES + 255) / 256, 256>>>((const int*)ei);
    accum_deg_kernel<<<(N_EDGES + 255) / 256, 256>>>(ei, ew);
    dinv_kernel<<<(N_NODES + 255) / 256, 256>>>();
    gemm_kernel<<<(N_NODES + GEMM_ROWS - 1) / GEMM_ROWS, GEMM_THREADS, GEMM_SMEM>>>(x, W, b, out);
    scatter_kernel<<<(N_EDGES * DC + 255) / 256, 256>>>(ei, ew, out);
}

// round 14
// speedup vs baseline: 1.8289x; 1.0654x over previous
#include <cuda_runtime.h>
#include <cuda_fp16.h>
#include <stdint.h>

#define N_NODES 50000
#define N_EDGES 800000
#define D 96
#define DC 24              // D / 4 (float4 chunks per row)
#define XS_STRIDE 25       // padded row stride in float4
#define GEMM_ROWS 128      // rows per block
#define GEMM_THREADS 192   // 12 col-groups x 16 row-groups
#define GEMM_SMEM ((D * DC + GEMM_ROWS * XS_STRIDE) * 16)  // Ws + Xs bytes

// Scratch (device globals; no allocation allowed)
__device__ int    g_is64;
__device__ float  g_deg[N_NODES];
__device__ __half g_h[(size_t)N_NODES * D];    // h * dinv[row], fp16

__device__ __forceinline__ int load_idx(const void* ei, size_t k) {
    return g_is64 ? (int)((const long long*)ei)[k] : ((const int*)ei)[k];
}

// packed f32x2 helpers (sm_103a FFMA2 — PTX only)
__device__ __forceinline__ unsigned long long pack2(float x, float y) {
    unsigned long long p;
    asm("mov.b64 %0, {%1, %2};" : "=l"(p) : "f"(x), "f"(y));
    return p;
}
__device__ __forceinline__ void fma2(unsigned long long& acc,
                                     unsigned long long a,
                                     unsigned long long b) {
    asm("fma.rn.f32x2 %0, %1, %2, %0;" : "+l"(acc) : "l"(a), "l"(b));
}
__device__ __forceinline__ void unpack2(unsigned long long p, float& x, float& y) {
    asm("mov.b64 {%0, %1}, %2;" : "=f"(x), "=f"(y) : "l"(p));
}

// ---------------------------------------------------------------------------
// 1. init: deg = 1 (self loop weight); thread 0 detects edge_index dtype.
//    int64 values < 2^31 have all-zero odd int32 words; random int32 ids don't.
// ---------------------------------------------------------------------------
__global__ void init_kernel(const int* __restrict__ ei32) {
    int i = blockIdx.x * blockDim.x + threadIdx.x;
    if (i < N_NODES) g_deg[i] = 1.0f;
    if (i == 0) {
        int looks64 = 1, any_nonzero = 0;
        #pragma unroll
        for (int k = 0; k < 64; k++) {
            if (ei32[2 * k + 1] != 0) looks64 = 0;
            if (ei32[2 * k] != 0) any_nonzero = 1;
        }
        g_is64 = (looks64 && any_nonzero) ? 1 : 0;
    }
}

// ---------------------------------------------------------------------------
// 2. deg[col] += ew
// ---------------------------------------------------------------------------
__global__ void accum_deg_kernel(const void* __restrict__ ei,
                                 const float* __restrict__ ew) {
    int e = blockIdx.x * blockDim.x + threadIdx.x;
    if (e < N_EDGES) {
        int col = load_idx(ei, (size_t)N_EDGES + e);
        atomicAdd(&g_deg[col], ew[e]);
    }
}

// ---------------------------------------------------------------------------
// 3. GEMM + epilogue:  h' = (x @ W) * dinv[row]  -> g_h (fp16)
//                      out[row] = b + h' * dinv[row]   (fp32, self loop + bias)
//    8x8 thread tiles, FFMA2 inner loop, 88KB dynamic smem.  (R8 config)
// ---------------------------------------------------------------------------
__global__ __launch_bounds__(GEMM_THREADS)
void gemm_kernel(const float* __restrict__ x, const float* __restrict__ W,
                 const float* __restrict__ b, float* __restrict__ out) {
    extern __shared__ float smem[];
    float4* Ws4 = (float4*)smem;                       // [D][DC]
    float4* Xs4 = (float4*)(smem + D * D);             // [GEMM_ROWS][XS_STRIDE]

    int tid = threadIdx.x;
    int row0 = blockIdx.x * GEMM_ROWS;

    const float4* W4 = (const float4*)W;
    #pragma unroll
    for (int i = tid; i < D * DC; i += GEMM_THREADS) Ws4[i] = W4[i];

    const float4* X4 = (const float4*)x;
    #pragma unroll
    for (int i = tid; i < GEMM_ROWS * DC; i += GEMM_THREADS) {
        int r = i / DC;
        int c = i - r * DC;
        int gr = row0 + r;
        Xs4[r * XS_STRIDE + c] = (gr < N_NODES) ? X4[(size_t)gr * DC + c]
                                                : make_float4(0.f, 0.f, 0.f, 0.f);
    }
    __syncthreads();

    int tx = tid % 12;       // col group: float4 chunks 2*tx, 2*tx+1
    int ty = tid / 12;       // row group 0..15
    int rbase = ty * 8;
    int c0 = 2 * tx, c1 = 2 * tx + 1;

    unsigned long long acc[8][4];
    #pragma unroll
    for (int r = 0; r < 8; r++)
        #pragma unroll
        for (int q = 0; q < 4; q++) acc[r][q] = 0ull;

    #pragma unroll 2
    for (int kc = 0; kc < DC; kc++) {
        float4 xv[8];
        #pragma unroll
        for (int r = 0; r < 8; r++) xv[r] = Xs4[(rbase + r) * XS_STRIDE + kc];
        #pragma unroll
        for (int kk = 0; kk < 4; kk++) {
            float4 wv0 = Ws4[(kc * 4 + kk) * DC + c0];
            float4 wv1 = Ws4[(kc * 4 + kk) * DC + c1];
            unsigned long long w0XY = pack2(wv0.x, wv0.y);
            unsigned long long w0ZW = pack2(wv0.z, wv0.w);
            unsigned long long w1XY = pack2(wv1.x, wv1.y);
            unsigned long long w1ZW = pack2(wv1.z, wv1.w);
            #pragma unroll
            for (int r = 0; r < 8; r++) {
                float a = ((const float*)&xv[r])[kk];
                unsigned long long aa = pack2(a, a);
                fma2(acc[r][0], aa, w0XY);
                fma2(acc[r][1], aa, w0ZW);
                fma2(acc[r][2], aa, w1XY);
                fma2(acc[r][3], aa, w1ZW);
            }
        }
    }

    float4 bv0 = ((const float4*)b)[c0];
    float4 bv1 = ((const float4*)b)[c1];
    uint2* H2 = (uint2*)g_h;            // one uint2 = 4 halves = one chunk
    float4* O4 = (float4*)out;
    #pragma unroll
    for (int r = 0; r < 8; r++) {
        int gr = row0 + rbase + r;
        if (gr < N_NODES) {
            float s = rsqrtf(g_deg[gr]);
            float4 h0, h1;
            unpack2(acc[r][0], h0.x, h0.y);
            unpack2(acc[r][1], h0.z, h0.w);
            unpack2(acc[r][2], h1.x, h1.y);
            unpack2(acc[r][3], h1.z, h1.w);
            h0.x *= s; h0.y *= s; h0.z *= s; h0.w *= s;
            h1.x *= s; h1.y *= s; h1.z *= s; h1.w *= s;
            // fp16 store of h' (edge messages); out stays fp32
            __half2 p00 = __floats2half2_rn(h0.x, h0.y);
            __half2 p01 = __floats2half2_rn(h0.z, h0.w);
            __half2 p10 = __floats2half2_rn(h1.x, h1.y);
            __half2 p11 = __floats2half2_rn(h1.z, h1.w);
            uint2 v0, v1;
            v0.x = *(uint32_t*)&p00; v0.y = *(uint32_t*)&p01;
            v1.x = *(uint32_t*)&p10; v1.y = *(uint32_t*)&p11;
            H2[(size_t)gr * DC + c0] = v0;
            H2[(size_t)gr * DC + c1] = v1;
            float4 o0, o1;   // b + h*dinv^2 (fp32 path)
            o0.x = bv0.x + h0.x * s; o0.y = bv0.y + h0.y * s;
            o0.z = bv0.z + h0.z * s; o0.w = bv0.w + h0.w * s;
            o1.x = bv1.x + h1.x * s; o1.y = bv1.y + h1.y * s;
            o1.z = bv1.z + h1.z * s; o1.w = bv1.w + h1.w * s;
            O4[(size_t)gr * DC + c0] = o0;
            O4[(size_t)gr * DC + c1] = o1;
        }
    }
}

// ---------------------------------------------------------------------------
// 4. Scatter (R8 mapping): thread t -> edge t/24, chunk t%24.
//    Loads fp16 h' chunk (8B), converts, scales, fp32 vector red to out.
// ---------------------------------------------------------------------------
__global__ __launch_bounds__(256)
void scatter_kernel(const void* __restrict__ ei,
                    const float* __restrict__ ew,
                    float* __restrict__ out) {
    int idx = blockIdx.x * blockDim.x + threadIdx.x;
    if (idx >= N_EDGES * DC) return;
    int e = idx / DC;
    int c = idx - e * DC;
    int row = load_idx(ei, e);
    int col = load_idx(ei, (size_t)N_EDGES + e);
    float nrm = ew[e] * rsqrtf(g_deg[col]);

    uint2 hv = ((const uint2*)g_h)[(size_t)row * DC + c];
    __half2 p0 = *(__half2*)&hv.x;
    __half2 p1 = *(__half2*)&hv.y;
    float2 f0 = __half22float2(p0);
    float2 f1 = __half22float2(p1);

    float mx = f0.x * nrm, my = f0.y * nrm, mz = f1.x * nrm, mw = f1.y * nrm;
    float* addr = out + (size_t)col * D + c * 4;
    asm volatile("red.global.add.v4.f32 [%0], {%1, %2, %3, %4};"
                 :: "l"(addr), "f"(mx), "f"(my), "f"(mz), "f"(mw)
                 : "memory");
}

// ---------------------------------------------------------------------------
// Launch.  Inputs: x[N*96] f32, edge_index[2*E] int32/int64, edge_weight[E] f32,
//                  W[96*96] f32, b[96] f32.  Output: [N*96] f32.
// ---------------------------------------------------------------------------
extern "C" void kernel_launch(void* const* d_in, const int* in_sizes, int n_in,
                              void* d_out, int out_size) {
    const float* x = (const float*)d_in[0];
    const void* ei = d_in[1];
    const float* ew = (const float*)d_in[2];
    const float* W = (const float*)d_in[3];
    const float* b = (const float*)d_in[4];
    float* out = (float*)d_out;

    static int smem_set = 0;
    if (!smem_set) {
        cudaFuncSetAttribute(gemm_kernel,
                             cudaFuncAttributeMaxDynamicSharedMemorySize,
                             GEMM_SMEM);
        smem_set = 1;
    }

    init_kernel<<<(N_NODES + 255) / 256, 256>>>((const int*)ei);
    accum_deg_kernel<<<(N_EDGES + 255) / 256, 256>>>(ei, ew);
    gemm_kernel<<<(N_NODES + GEMM_ROWS - 1) / GEMM_ROWS, GEMM_THREADS, GEMM_SMEM>>>(x, W, b, out);
    scatter_kernel<<<(N_EDGES * DC + 255) / 256, 256>>>(ei, ew, out);
}